// round 14
// baseline (speedup 1.0000x reference)
#include <cuda_runtime.h>
#include <cstdint>
#include <math.h>

#define N 4096
#define D 128
#define NS 75
#define NC 8                     // candidate sigmas kept for exact pass
#define NSLOT 32                 // atomic accumulator slots
#define LOG2E 1.4426950408889634f

// ---------------- scratch (device globals; no runtime allocation) ----------
__device__ float g_d2[(size_t)N * N];      // upper-triangle tiles + diagonal tiles

struct Accum {
    double sum_dist;
    unsigned long long nz;
    double S1[NSLOT][NS], S2[NSLOT][NS];   // pass-1 sums, slot-spread
    double T1[NSLOT][NC], T2[NSLOT][NC];   // pass-2 exact sums, slot-spread
    int    cand[NC];
    float  candc[NC];
};
__device__ Accum g_acc;                    // zeroed via cudaMemsetAsync per launch

// ---------------- tf32 helpers ----------------------------------------------
__device__ __forceinline__ uint32_t f2tf32(float f) {
    uint32_t u;
    asm("cvt.rna.tf32.f32 %0, %1;" : "=r"(u) : "f"(f));
    return u;
}
// hi part as fp32 value (tf32 bit pattern is a valid fp32)
__device__ __forceinline__ float tf32_hi(float v) {
    return __uint_as_float(f2tf32(v));
}
__device__ __forceinline__ float tf32_lo(float v, float hi) {
    return __uint_as_float(f2tf32(v - hi));
}

#define MMA_TF32(dd, a, b)                                                     \
    asm volatile("mma.sync.aligned.m16n8k8.row.col.f32.tf32.tf32.f32 "         \
        "{%0,%1,%2,%3}, {%4,%5,%6,%7}, {%8,%9}, {%0,%1,%2,%3};"                \
        : "+f"((dd)[0]), "+f"((dd)[1]), "+f"((dd)[2]), "+f"((dd)[3])           \
        : "r"((a)[0]), "r"((a)[1]), "r"((a)[2]), "r"((a)[3]),                  \
          "r"((b)[0]), "r"((b)[1]))

// ---------------- d2 GEMM: 3xTF32 tensor-core Gram tiles -------------------
// 128x128 output tile per block, 256 threads (8 warps, 2x4 warp grid of
// 64x32 sub-tiles). K staged in 16-wide hi/lo chunks, stride-20 smem rows
// (conflict-free fragment LDS). Scalar-FFMA wall (76us) bypassed.
__global__ __launch_bounds__(256) void k_d2(const float* __restrict__ x) {
    int b = blockIdx.x;
    float bf = (sqrtf(8.0f * (float)b + 1.0f) - 1.0f) * 0.5f;
    int bi = (int)bf;
    while ((bi + 1) * (bi + 2) / 2 <= b) bi++;
    while (bi * (bi + 1) / 2 > b) bi--;
    int bj = b - bi * (bi + 1) / 2;           // bi >= bj

    __shared__ __align__(16) float Ah[128][20];
    __shared__ __align__(16) float Al[128][20];
    __shared__ __align__(16) float Bh[128][20];
    __shared__ __align__(16) float Bl[128][20];

    int tid = threadIdx.x;
    int w = tid >> 5, lane = tid & 31;
    int wm = w >> 2, wn = w & 3;              // warp tile origin (wm*64, wn*32)
    int g = lane >> 2, t = lane & 3;

    const float* Ab = x + (size_t)bi * 128 * D;
    const float* Bb = x + (size_t)bj * 128 * D;

    float dacc[4][4][4];
    #pragma unroll
    for (int mt = 0; mt < 4; mt++)
        #pragma unroll
        for (int nt = 0; nt < 4; nt++)
            #pragma unroll
            for (int r = 0; r < 4; r++) dacc[mt][nt][r] = 0.0f;

    int srow = tid >> 1;                      // staging row 0..127
    int skq = (tid & 1) * 8;                  // staging k offset 0 or 8
    float sa = 0.0f, sb = 0.0f;               // half-row norm partials

    for (int k0 = 0; k0 < D; k0 += 16) {
        #pragma unroll
        for (int q = 0; q < 2; q++) {
            int kk = skq + q * 4;
            float4 av = *(const float4*)(Ab + (size_t)srow * D + k0 + kk);
            float4 bv = *(const float4*)(Bb + (size_t)srow * D + k0 + kk);
            sa = fmaf(av.x, av.x, fmaf(av.y, av.y, fmaf(av.z, av.z, fmaf(av.w, av.w, sa))));
            sb = fmaf(bv.x, bv.x, fmaf(bv.y, bv.y, fmaf(bv.z, bv.z, fmaf(bv.w, bv.w, sb))));
            float ahx = tf32_hi(av.x), ahy = tf32_hi(av.y), ahz = tf32_hi(av.z), ahw = tf32_hi(av.w);
            float bhx = tf32_hi(bv.x), bhy = tf32_hi(bv.y), bhz = tf32_hi(bv.z), bhw = tf32_hi(bv.w);
            *(float4*)&Ah[srow][kk] = make_float4(ahx, ahy, ahz, ahw);
            *(float4*)&Al[srow][kk] = make_float4(tf32_lo(av.x, ahx), tf32_lo(av.y, ahy),
                                                  tf32_lo(av.z, ahz), tf32_lo(av.w, ahw));
            *(float4*)&Bh[srow][kk] = make_float4(bhx, bhy, bhz, bhw);
            *(float4*)&Bl[srow][kk] = make_float4(tf32_lo(bv.x, bhx), tf32_lo(bv.y, bhy),
                                                  tf32_lo(bv.z, bhz), tf32_lo(bv.w, bhw));
        }
        __syncthreads();

        #pragma unroll
        for (int ks = 0; ks < 2; ks++) {
            int kb = ks * 8;
            uint32_t fah[4][4], fal[4][4];
            #pragma unroll
            for (int mt = 0; mt < 4; mt++) {
                int r0 = wm * 64 + mt * 16;
                fah[mt][0] = __float_as_uint(Ah[r0 + g][kb + t]);
                fah[mt][1] = __float_as_uint(Ah[r0 + g + 8][kb + t]);
                fah[mt][2] = __float_as_uint(Ah[r0 + g][kb + t + 4]);
                fah[mt][3] = __float_as_uint(Ah[r0 + g + 8][kb + t + 4]);
                fal[mt][0] = __float_as_uint(Al[r0 + g][kb + t]);
                fal[mt][1] = __float_as_uint(Al[r0 + g + 8][kb + t]);
                fal[mt][2] = __float_as_uint(Al[r0 + g][kb + t + 4]);
                fal[mt][3] = __float_as_uint(Al[r0 + g + 8][kb + t + 4]);
            }
            uint32_t fbh[4][2], fbl[4][2];
            #pragma unroll
            for (int nt = 0; nt < 4; nt++) {
                int c0 = wn * 32 + nt * 8;
                fbh[nt][0] = __float_as_uint(Bh[c0 + g][kb + t]);
                fbh[nt][1] = __float_as_uint(Bh[c0 + g][kb + t + 4]);
                fbl[nt][0] = __float_as_uint(Bl[c0 + g][kb + t]);
                fbl[nt][1] = __float_as_uint(Bl[c0 + g][kb + t + 4]);
            }
            #pragma unroll
            for (int mt = 0; mt < 4; mt++)
                #pragma unroll
                for (int nt = 0; nt < 4; nt++) {
                    MMA_TF32(dacc[mt][nt], fah[mt], fbh[nt]);  // hi*hi
                    MMA_TF32(dacc[mt][nt], fah[mt], fbl[nt]);  // hi*lo
                    MMA_TF32(dacc[mt][nt], fal[mt], fbh[nt]);  // lo*hi
                }
        }
        __syncthreads();
    }

    // publish row norms (pairs tid, tid^1 share row srow); reuse Al/Bl
    sa += __shfl_xor_sync(0xffffffffu, sa, 1);
    sb += __shfl_xor_sync(0xffffffffu, sb, 1);
    float* sqA = &Al[0][0];
    float* sqB = &Bl[0][0];
    if ((tid & 1) == 0) { sqA[srow] = sa; sqB[srow] = sb; }
    __syncthreads();

    float sd = 0.0f;
    int cnt = 0;
    bool diag = (bi == bj);

    #pragma unroll
    for (int mt = 0; mt < 4; mt++) {
        #pragma unroll
        for (int nt = 0; nt < 4; nt++) {
            int rr0 = wm * 64 + mt * 16 + g;       // row within A block
            int rr1 = rr0 + 8;
            int cc  = wn * 32 + nt * 8 + 2 * t;    // col within B block
            float qi0 = sqA[rr0], qi1 = sqA[rr1];
            float qj0 = sqB[cc],  qj1 = sqB[cc + 1];
            float v00 = fmaxf(qi0 + qj0 - 2.0f * dacc[mt][nt][0], 0.0f);
            float v01 = fmaxf(qi0 + qj1 - 2.0f * dacc[mt][nt][1], 0.0f);
            float v10 = fmaxf(qi1 + qj0 - 2.0f * dacc[mt][nt][2], 0.0f);
            float v11 = fmaxf(qi1 + qj1 - 2.0f * dacc[mt][nt][3], 0.0f);
            if (v00 > 0.0f) { sd += sqrtf(v00); cnt++; }
            if (v01 > 0.0f) { sd += sqrtf(v01); cnt++; }
            if (v10 > 0.0f) { sd += sqrtf(v10); cnt++; }
            if (v11 > 0.0f) { sd += sqrtf(v11); cnt++; }
            if (diag) {
                *(float2*)&g_d2[(size_t)(bi * 128 + rr0) * N + bj * 128 + cc] = make_float2(v00, v01);
                *(float2*)&g_d2[(size_t)(bi * 128 + rr1) * N + bj * 128 + cc] = make_float2(v10, v11);
            } else {
                // upper-triangle tile: rows = bj block (cols), cols = bi block (rows)
                g_d2[(size_t)(bj * 128 + cc)     * N + bi * 128 + rr0] = v00;
                g_d2[(size_t)(bj * 128 + cc + 1) * N + bi * 128 + rr0] = v01;
                g_d2[(size_t)(bj * 128 + cc)     * N + bi * 128 + rr1] = v10;
                g_d2[(size_t)(bj * 128 + cc + 1) * N + bi * 128 + rr1] = v11;
            }
        }
    }

    #pragma unroll
    for (int o = 16; o; o >>= 1) {
        sd  += __shfl_xor_sync(0xffffffffu, sd, o);
        cnt += __shfl_xor_sync(0xffffffffu, cnt, o);
    }
    __shared__ float ssd[8];
    __shared__ int   scn[8];
    if (lane == 0) { ssd[w] = sd; scn[w] = cnt; }
    __syncthreads();
    if (tid == 0) {
        float S = 0.0f; long long C = 0;
        #pragma unroll
        for (int i = 0; i < 8; i++) { S += ssd[i]; C += scn[i]; }
        double wgt = diag ? 1.0 : 2.0;
        atomicAdd(&g_acc.sum_dist, wgt * (double)S);
        atomicAdd(&g_acc.nz, (unsigned long long)((diag ? 1 : 2) * C));
    }
}

// ---------------- PASS 1: screening sweep on contiguous 256-elem windows ---
// 1/16 deterministic subsample; window offset (p&15)*255 spans the pair.
__global__ __launch_bounds__(512, 3) void k_sweep1(const float* __restrict__ L) {
    __shared__ float2 sDL[256];
    __shared__ float sc[80];

    int tid = threadIdx.x;
    int bid = blockIdx.x;

    if (tid < 80) {
        float mean = (float)(g_acc.sum_dist / (double)g_acc.nz);
        float lo = 0.1f * mean;
        float st = (10.0f * mean - lo) / (float)NS;
        float s = lo + st * (float)tid;
        sc[tid] = (tid < NS) ? LOG2E / (s * s) : 0.0f;
    }

    int w = tid >> 5, lane = tid & 31;

    if (bid >= N / 2) {
        // ---- diagonal block for sigma j (scaled 0.0625) ----
        __syncthreads();
        int j = bid - N / 2;
        float c = sc[j];
        float s1 = 0.0f, s2 = 0.0f;
        for (int i = tid; i < N; i += 512) {
            float d = g_d2[(size_t)i * N + i];
            float l = L[(size_t)i * N + i];
            float K = exp2f(-d * c);
            s1 = fmaf(K, l, s1);
            s2 = fmaf(K, K, s2);
        }
        #pragma unroll
        for (int o = 16; o; o >>= 1) {
            s1 += __shfl_xor_sync(0xffffffffu, s1, o);
            s2 += __shfl_xor_sync(0xffffffffu, s2, o);
        }
        __shared__ float sh1[16], sh2[16];
        if (lane == 0) { sh1[w] = s1; sh2[w] = s2; }
        __syncthreads();
        if (tid == 0) {
            float a = 0.0f, bq = 0.0f;
            #pragma unroll
            for (int i = 0; i < 16; i++) { a += sh1[i]; bq += sh2[i]; }
            atomicAdd(&g_acc.S1[j & (NSLOT - 1)][j], 0.0625 * (double)a);
            atomicAdd(&g_acc.S2[j & (NSLOT - 1)][j], 0.0625 * (double)bq);
        }
        return;
    }

    int slot = bid & (NSLOT - 1);
    int p = bid;
    int r0 = p, r1 = N - 1 - p;
    int len0 = N - 1 - r0;
    int s0 = (p & 15) * 255;              // offsets 0,255,...,3825

    const float* D0 = g_d2 + (size_t)r0 * N + (r0 + 1);
    const float* L0 = L    + (size_t)r0 * N + (r0 + 1);
    const float* D1 = g_d2 + (size_t)r1 * N + (r1 + 1);
    const float* L1 = L    + (size_t)r1 * N + (r1 + 1);

    if (tid < 256) {
        int e = s0 + tid;
        float d, l;
        if (e < len0) { d = D0[e]; l = L0[e]; }
        else          { d = D1[e - len0]; l = L1[e - len0]; }
        sDL[tid] = make_float2(-d, l);
    }
    __syncthreads();

    bool has5 = (w < 11);
    float c[5], a1[5], a2[5];
    #pragma unroll
    for (int j = 0; j < 4; j++) { c[j] = sc[w + 16 * j]; a1[j] = 0.0f; a2[j] = 0.0f; }
    c[4] = has5 ? sc[64 + w] : 0.0f;
    a1[4] = 0.0f; a2[4] = 0.0f;

    if (has5) {
        for (int e = lane; e < 256; e += 32) {
            float2 dl = sDL[e];
            #pragma unroll
            for (int j = 0; j < 5; j++) {
                float K;
                asm("ex2.approx.ftz.f32 %0, %1;" : "=f"(K) : "f"(dl.x * c[j]));
                a1[j] = fmaf(K, dl.y, a1[j]);
                a2[j] = fmaf(K, K,  a2[j]);
            }
        }
    } else {
        for (int e = lane; e < 256; e += 32) {
            float2 dl = sDL[e];
            #pragma unroll
            for (int j = 0; j < 4; j++) {
                float K;
                asm("ex2.approx.ftz.f32 %0, %1;" : "=f"(K) : "f"(dl.x * c[j]));
                a1[j] = fmaf(K, dl.y, a1[j]);
                a2[j] = fmaf(K, K,  a2[j]);
            }
        }
    }

    #pragma unroll
    for (int j = 0; j < 5; j++) {
        float v1 = a1[j], v2 = a2[j];
        #pragma unroll
        for (int o = 16; o; o >>= 1) {
            v1 += __shfl_xor_sync(0xffffffffu, v1, o);
            v2 += __shfl_xor_sync(0xffffffffu, v2, o);
        }
        if (lane == 0 && (j < 4 || has5)) {
            int idx = (j < 4) ? (w + 16 * j) : (64 + w);
            atomicAdd(&g_acc.S1[slot][idx], 2.0 * (double)v1);
            atomicAdd(&g_acc.S2[slot][idx], 2.0 * (double)v2);
        }
    }
}

// ---------------- fold slots + pick top-NC candidates ----------------------
__global__ void k_pick() {
    __shared__ double sL[NS];
    int j = threadIdx.x;
    if (j < NS) {
        double s1 = 0.0, s2 = 0.0;
        for (int s = 0; s < NSLOT; s++) { s1 += g_acc.S1[s][j]; s2 += g_acc.S2[s][j]; }
        sL[j] = s1 / sqrt(s2);
    }
    __syncthreads();
    if (j != 0) return;

    float mean = (float)(g_acc.sum_dist / (double)g_acc.nz);
    float lo = 0.1f * mean;
    float st = (10.0f * mean - lo) / (float)NS;

    bool used[NS];
    for (int i = 0; i < NS; i++) used[i] = false;
    int sel[NC];
    for (int r = 0; r < NC; r++) {
        double best = -1.0e300; int bi = 0;
        for (int i = 0; i < NS; i++)
            if (!used[i] && sL[i] > best) { best = sL[i]; bi = i; }
        used[bi] = true;
        sel[r] = bi;
    }
    for (int i = 1; i < NC; i++) {              // sort ascending (first-max semantics)
        int v = sel[i], k = i;
        while (k > 0 && sel[k - 1] > v) { sel[k] = sel[k - 1]; k--; }
        sel[k] = v;
    }
    for (int r = 0; r < NC; r++) {
        g_acc.cand[r] = sel[r];
        float s = lo + st * (float)sel[r];
        g_acc.candc[r] = LOG2E / (s * s);
    }
}

// ---------------- PASS 2: exact sums for the NC candidates (R11 form) ------
__global__ __launch_bounds__(512, 3) void k_sweep2(const float* __restrict__ L) {
    __shared__ float2 sDL[N];     // 4095 used
    __shared__ float scc[NC];

    int tid = threadIdx.x;
    int bid = blockIdx.x;

    if (tid < NC) scc[tid] = g_acc.candc[tid];

    int w = tid >> 5, lane = tid & 31;

    if (bid >= N / 2) {
        __syncthreads();
        int k = bid - N / 2;
        float c = scc[k];
        float s1 = 0.0f, s2 = 0.0f;
        for (int i = tid; i < N; i += 512) {
            float d = g_d2[(size_t)i * N + i];
            float l = L[(size_t)i * N + i];
            float K = exp2f(-d * c);
            s1 = fmaf(K, l, s1);
            s2 = fmaf(K, K, s2);
        }
        #pragma unroll
        for (int o = 16; o; o >>= 1) {
            s1 += __shfl_xor_sync(0xffffffffu, s1, o);
            s2 += __shfl_xor_sync(0xffffffffu, s2, o);
        }
        __shared__ float sh1[16], sh2[16];
        if (lane == 0) { sh1[w] = s1; sh2[w] = s2; }
        __syncthreads();
        if (tid == 0) {
            float a = 0.0f, bq = 0.0f;
            #pragma unroll
            for (int i = 0; i < 16; i++) { a += sh1[i]; bq += sh2[i]; }
            atomicAdd(&g_acc.T1[k & (NSLOT - 1)][k], (double)a);
            atomicAdd(&g_acc.T2[k & (NSLOT - 1)][k], (double)bq);
        }
        return;
    }

    int slot = bid & (NSLOT - 1);
    int p = bid;
    int r0 = p, r1 = N - 1 - p;
    int len0 = N - 1 - r0;

    const float* Dr0 = g_d2 + (size_t)r0 * N;
    const float* Lr0 = L    + (size_t)r0 * N;
    const float* Dr1 = g_d2 + (size_t)r1 * N;
    const float* Lr1 = L    + (size_t)r1 * N;

    int c00 = r0 + 1;
    for (int i4 = (c00 & ~3) + tid * 4; i4 < N; i4 += 512 * 4) {
        float4 d = *(const float4*)(Dr0 + i4);
        float4 l = *(const float4*)(Lr0 + i4);
        float dv[4] = {d.x, d.y, d.z, d.w};
        float lv[4] = {l.x, l.y, l.z, l.w};
        #pragma unroll
        for (int j = 0; j < 4; j++) {
            int col = i4 + j;
            if (col >= c00) sDL[col - c00] = make_float2(-dv[j], lv[j]);
        }
    }
    int c10 = r1 + 1;
    for (int i4 = (c10 & ~3) + tid * 4; i4 < N; i4 += 512 * 4) {
        float4 d = *(const float4*)(Dr1 + i4);
        float4 l = *(const float4*)(Lr1 + i4);
        float dv[4] = {d.x, d.y, d.z, d.w};
        float lv[4] = {l.x, l.y, l.z, l.w};
        #pragma unroll
        for (int j = 0; j < 4; j++) {
            int col = i4 + j;
            if (col >= c10) sDL[len0 + col - c10] = make_float2(-dv[j], lv[j]);
        }
    }
    __syncthreads();

    int k = w & 7;
    float c = scc[k];
    float a1 = 0.0f, a2 = 0.0f, b1 = 0.0f, b2 = 0.0f;
    int base = lane + 32 * (w >> 3);
    for (int e = base; e < N - 1; e += 128) {
        float2 dl = sDL[e];
        float K;
        asm("ex2.approx.ftz.f32 %0, %1;" : "=f"(K) : "f"(dl.x * c));
        a1 = fmaf(K, dl.y, a1);
        a2 = fmaf(K, K, a2);
        int e2 = e + 64;
        if (e2 < N - 1) {
            float2 dl2 = sDL[e2];
            float K2;
            asm("ex2.approx.ftz.f32 %0, %1;" : "=f"(K2) : "f"(dl2.x * c));
            b1 = fmaf(K2, dl2.y, b1);
            b2 = fmaf(K2, K2, b2);
        }
    }
    a1 += b1; a2 += b2;
    #pragma unroll
    for (int o = 16; o; o >>= 1) {
        a1 += __shfl_xor_sync(0xffffffffu, a1, o);
        a2 += __shfl_xor_sync(0xffffffffu, a2, o);
    }
    if (lane == 0) {
        atomicAdd(&g_acc.T1[slot][k], 2.0 * (double)a1);
        atomicAdd(&g_acc.T2[slot][k], 2.0 * (double)a2);
    }
}

// ---------------- output: A = exp(-d2/sigma^2)/n, triangular + mirror ------
__global__ __launch_bounds__(256) void k_out(float* __restrict__ out) {
    __shared__ float s_cc;
    int tid = threadIdx.x;

    if (tid == 0) {
        float mean = (float)(g_acc.sum_dist / (double)g_acc.nz);
        float lo = 0.1f * mean;
        float st = (10.0f * mean - lo) / (float)NS;
        double best = -1.0e300;
        int bidx = 0;
        #pragma unroll 1
        for (int k = 0; k < NC; k++) {
            double t1 = 0.0, t2 = 0.0;
            for (int s = 0; s < NSLOT; s++) { t1 += g_acc.T1[s][k]; t2 += g_acc.T2[s][k]; }
            double l = t1 / sqrt(t2);
            if (l > best) { best = l; bidx = g_acc.cand[k]; }
        }
        float s = lo + st * (float)bidx;
        s_cc = -LOG2E / (s * s);
    }
    __syncthreads();
    float cc = s_cc;
    const float inv_n = 1.0f / (float)N;

    int b = blockIdx.x;
    float bf = (sqrtf(8.0f * (float)b + 1.0f) - 1.0f) * 0.5f;
    int bi = (int)bf;
    while ((bi + 1) * (bi + 2) / 2 <= b) bi++;
    while (bi * (bi + 1) / 2 > b) bi--;
    int bj = b - bi * (bi + 1) / 2;           // bi >= bj
    int tr = bj, tc = bi;

    if (tr == tc) {
        #pragma unroll
        for (int it = 0; it < 16; it++) {
            int e = (it * 256 + tid) * 4;
            int row = e >> 7;
            int col = e & 127;
            size_t g = (size_t)(tr * 128 + row) * N + tc * 128 + col;
            float4 d = *(const float4*)(g_d2 + g);
            float4 r;
            asm("ex2.approx.ftz.f32 %0, %1;" : "=f"(r.x) : "f"(d.x * cc));
            asm("ex2.approx.ftz.f32 %0, %1;" : "=f"(r.y) : "f"(d.y * cc));
            asm("ex2.approx.ftz.f32 %0, %1;" : "=f"(r.z) : "f"(d.z * cc));
            asm("ex2.approx.ftz.f32 %0, %1;" : "=f"(r.w) : "f"(d.w * cc));
            r.x *= inv_n; r.y *= inv_n; r.z *= inv_n; r.w *= inv_n;
            *(float4*)(out + g) = r;
        }
        return;
    }

    __shared__ float sT[64][65];
    #pragma unroll
    for (int q = 0; q < 4; q++) {
        int qr = q >> 1, qc = q & 1;
        int rbase = tr * 128 + qr * 64;
        int cbase = tc * 128 + qc * 64;
        #pragma unroll
        for (int it = 0; it < 4; it++) {
            int idx = it * 256 + tid;
            int row = idx >> 4;
            int col = (idx & 15) * 4;
            size_t g = (size_t)(rbase + row) * N + cbase + col;
            float4 d = *(const float4*)(g_d2 + g);
            float4 r;
            asm("ex2.approx.ftz.f32 %0, %1;" : "=f"(r.x) : "f"(d.x * cc));
            asm("ex2.approx.ftz.f32 %0, %1;" : "=f"(r.y) : "f"(d.y * cc));
            asm("ex2.approx.ftz.f32 %0, %1;" : "=f"(r.z) : "f"(d.z * cc));
            asm("ex2.approx.ftz.f32 %0, %1;" : "=f"(r.w) : "f"(d.w * cc));
            r.x *= inv_n; r.y *= inv_n; r.z *= inv_n; r.w *= inv_n;
            *(float4*)(out + g) = r;
            sT[row][col + 0] = r.x; sT[row][col + 1] = r.y;
            sT[row][col + 2] = r.z; sT[row][col + 3] = r.w;
        }
        __syncthreads();
        #pragma unroll
        for (int it = 0; it < 4; it++) {
            int idx = it * 256 + tid;
            int row = idx >> 4;
            int col = (idx & 15) * 4;
            size_t g = (size_t)(cbase + row) * N + rbase + col;
            float4 r = make_float4(sT[col + 0][row], sT[col + 1][row],
                                   sT[col + 2][row], sT[col + 3][row]);
            *(float4*)(out + g) = r;
        }
        __syncthreads();
    }
}

// ---------------- launch ----------------------------------------------------
extern "C" void kernel_launch(void* const* d_in, const int* in_sizes, int n_in,
                              void* d_out, int out_size) {
    (void)in_sizes; (void)n_in; (void)out_size;
    const float* x = (const float*)d_in[0];
    const float* L = (const float*)d_in[1];
    float* out = (float*)d_out;

    void* acc_ptr = nullptr;
    cudaGetSymbolAddress(&acc_ptr, g_acc);
    cudaMemsetAsync(acc_ptr, 0, sizeof(Accum));

    k_d2<<<(32 * 33) / 2, 256>>>(x);           // 528 tiles, 3xTF32 tensor cores
    k_sweep1<<<N / 2 + NS, 512>>>(L);          // screening: 1/16 windows
    k_pick<<<1, 128>>>();                      // fold slots + top-8 candidates
    k_sweep2<<<N / 2 + NC, 512>>>(L);          // exact sums, 8 candidates
    k_out<<<(32 * 33) / 2, 256>>>(out);        // tiles + mirrors (+exact argmax)
}

// round 15
// speedup vs baseline: 1.1378x; 1.1378x over previous
#include <cuda_runtime.h>
#include <cstdint>
#include <math.h>

#define N 4096
#define D 128
#define NS 75
#define NC 4                     // candidate sigmas kept for exact pass
#define NSLOT 32                 // atomic accumulator slots
#define LOG2E 1.4426950408889634f

// ---------------- scratch (device globals; no runtime allocation) ----------
__device__ float g_d2[(size_t)N * N];      // upper-triangle tiles + diagonal tiles

struct Accum {
    double sum_dist;
    unsigned long long nz;
    double S1[NSLOT][NS], S2[NSLOT][NS];   // pass-1 sums, slot-spread
    double T1[NSLOT][NC], T2[NSLOT][NC];   // pass-2 exact sums, slot-spread
    int    cand[NC];
    float  candc[NC];
};
__device__ Accum g_acc;                    // zeroed via cudaMemsetAsync per launch

// bank-swizzle: row r (0..127) -> physical float index
__device__ __forceinline__ int swz(int r) {
    int q = r >> 2;
    return (((q ^ (q >> 3)) << 2) | (r & 3));
}
__device__ __forceinline__ int swzq(int q) {
    return (q ^ (q >> 3)) << 2;
}

// ---------------- d2 GEMM (scalar FFMA, proven 76us; R10 form) -------------
__global__ __launch_bounds__(256) void k_d2(const float* __restrict__ x) {
    int b = blockIdx.x;
    float bf = (sqrtf(8.0f * (float)b + 1.0f) - 1.0f) * 0.5f;
    int bi = (int)bf;
    while ((bi + 1) * (bi + 2) / 2 <= b) bi++;
    while (bi * (bi + 1) / 2 > b) bi--;
    int bj = b - bi * (bi + 1) / 2;           // bi >= bj

    __shared__ __align__(16) float As[8][128];
    __shared__ __align__(16) float Bs[8][128];

    int tid = threadIdx.x;
    int tx = tid & 15;
    int ty = tid >> 4;
    int lr = tid >> 1;
    int lc = (tid & 1) * 4;

    const float* Ab = x + (size_t)bi * 128 * D;
    const float* Bb = x + (size_t)bj * 128 * D;

    float acc[8][8];
    #pragma unroll
    for (int m = 0; m < 8; m++)
        #pragma unroll
        for (int n = 0; n < 8; n++) acc[m][n] = 0.0f;

    float sa = 0.0f, sb = 0.0f;
    int plr = swz(lr);

    const int pqa0 = swzq(ty * 2), pqa1 = swzq(ty * 2 + 1);
    const int pqb0 = swzq(tx * 2), pqb1 = swzq(tx * 2 + 1);

    for (int k0 = 0; k0 < D; k0 += 8) {
        float4 av = *(const float4*)(Ab + (size_t)lr * D + k0 + lc);
        float4 bv = *(const float4*)(Bb + (size_t)lr * D + k0 + lc);
        sa = fmaf(av.x, av.x, fmaf(av.y, av.y, fmaf(av.z, av.z, fmaf(av.w, av.w, sa))));
        sb = fmaf(bv.x, bv.x, fmaf(bv.y, bv.y, fmaf(bv.z, bv.z, fmaf(bv.w, bv.w, sb))));
        As[lc + 0][plr] = av.x; As[lc + 1][plr] = av.y;
        As[lc + 2][plr] = av.z; As[lc + 3][plr] = av.w;
        Bs[lc + 0][plr] = bv.x; Bs[lc + 1][plr] = bv.y;
        Bs[lc + 2][plr] = bv.z; Bs[lc + 3][plr] = bv.w;
        __syncthreads();
        #pragma unroll
        for (int k = 0; k < 8; k++) {
            float4 a0 = *(const float4*)&As[k][pqa0];
            float4 a1 = *(const float4*)&As[k][pqa1];
            float4 b0 = *(const float4*)&Bs[k][pqb0];
            float4 b1 = *(const float4*)&Bs[k][pqb1];
            float a[8] = {a0.x, a0.y, a0.z, a0.w, a1.x, a1.y, a1.z, a1.w};
            float bb[8] = {b0.x, b0.y, b0.z, b0.w, b1.x, b1.y, b1.z, b1.w};
            #pragma unroll
            for (int m = 0; m < 8; m++)
                #pragma unroll
                for (int n = 0; n < 8; n++)
                    acc[m][n] = fmaf(a[m], bb[n], acc[m][n]);
        }
        __syncthreads();
    }

    sa += __shfl_xor_sync(0xffffffffu, sa, 1);
    sb += __shfl_xor_sync(0xffffffffu, sb, 1);
    float* sqA = &As[0][0];
    float* sqB = &Bs[0][0];
    if ((tid & 1) == 0) { sqA[lr] = sa; sqB[lr] = sb; }
    __syncthreads();

    int row0 = bi * 128 + ty * 8;
    int col0 = bj * 128 + tx * 8;
    float sqi[8], sqj[8];
    #pragma unroll
    for (int m = 0; m < 8; m++) sqi[m] = sqA[ty * 8 + m];
    #pragma unroll
    for (int n = 0; n < 8; n++) sqj[n] = sqB[tx * 8 + n];

    float sd = 0.0f;
    int cnt = 0;

    if (bi == bj) {
        #pragma unroll
        for (int m = 0; m < 8; m++) {
            float v[8];
            #pragma unroll
            for (int n = 0; n < 8; n++) {
                float dd = fmaxf(sqi[m] + sqj[n] - 2.0f * acc[m][n], 0.0f);
                v[n] = dd;
                if (dd > 0.0f) { sd += sqrtf(dd); cnt++; }
            }
            float4* p = (float4*)&g_d2[(size_t)(row0 + m) * N + col0];
            p[0] = make_float4(v[0], v[1], v[2], v[3]);
            p[1] = make_float4(v[4], v[5], v[6], v[7]);
        }
    } else {
        #pragma unroll
        for (int n = 0; n < 8; n++) {
            float t[8];
            #pragma unroll
            for (int m = 0; m < 8; m++) {
                float dd = fmaxf(sqi[m] + sqj[n] - 2.0f * acc[m][n], 0.0f);
                t[m] = dd;
                if (dd > 0.0f) { sd += sqrtf(dd); cnt++; }
            }
            float4* p = (float4*)&g_d2[(size_t)(col0 + n) * N + row0];
            p[0] = make_float4(t[0], t[1], t[2], t[3]);
            p[1] = make_float4(t[4], t[5], t[6], t[7]);
        }
    }

    #pragma unroll
    for (int o = 16; o; o >>= 1) {
        sd  += __shfl_xor_sync(0xffffffffu, sd, o);
        cnt += __shfl_xor_sync(0xffffffffu, cnt, o);
    }
    __shared__ float ssd[8];
    __shared__ int   scn[8];
    int wid = tid >> 5;
    if ((tid & 31) == 0) { ssd[wid] = sd; scn[wid] = cnt; }
    __syncthreads();
    if (tid == 0) {
        float S = 0.0f; long long C = 0;
        #pragma unroll
        for (int i = 0; i < 8; i++) { S += ssd[i]; C += scn[i]; }
        double w = (bi == bj) ? 1.0 : 2.0;
        atomicAdd(&g_acc.sum_dist, w * (double)S);
        atomicAdd(&g_acc.nz, (unsigned long long)((bi == bj ? 1 : 2) * C));
    }
}

// ---------------- PASS 1: screening sweep on contiguous 256-elem windows ---
// 1/16 deterministic subsample; window offset (p&15)*255 spans the pair.
__global__ __launch_bounds__(512, 3) void k_sweep1(const float* __restrict__ L) {
    __shared__ float2 sDL[256];
    __shared__ float sc[80];

    int tid = threadIdx.x;
    int bid = blockIdx.x;

    if (tid < 80) {
        float mean = (float)(g_acc.sum_dist / (double)g_acc.nz);
        float lo = 0.1f * mean;
        float st = (10.0f * mean - lo) / (float)NS;
        float s = lo + st * (float)tid;
        sc[tid] = (tid < NS) ? LOG2E / (s * s) : 0.0f;
    }

    int w = tid >> 5, lane = tid & 31;

    if (bid >= N / 2) {
        // ---- diagonal block for sigma j (scaled 0.0625) ----
        __syncthreads();
        int j = bid - N / 2;
        float c = sc[j];
        float s1 = 0.0f, s2 = 0.0f;
        for (int i = tid; i < N; i += 512) {
            float d = g_d2[(size_t)i * N + i];
            float l = L[(size_t)i * N + i];
            float K = exp2f(-d * c);
            s1 = fmaf(K, l, s1);
            s2 = fmaf(K, K, s2);
        }
        #pragma unroll
        for (int o = 16; o; o >>= 1) {
            s1 += __shfl_xor_sync(0xffffffffu, s1, o);
            s2 += __shfl_xor_sync(0xffffffffu, s2, o);
        }
        __shared__ float sh1[16], sh2[16];
        if (lane == 0) { sh1[w] = s1; sh2[w] = s2; }
        __syncthreads();
        if (tid == 0) {
            float a = 0.0f, bq = 0.0f;
            #pragma unroll
            for (int i = 0; i < 16; i++) { a += sh1[i]; bq += sh2[i]; }
            atomicAdd(&g_acc.S1[j & (NSLOT - 1)][j], 0.0625 * (double)a);
            atomicAdd(&g_acc.S2[j & (NSLOT - 1)][j], 0.0625 * (double)bq);
        }
        return;
    }

    int slot = bid & (NSLOT - 1);
    int p = bid;
    int r0 = p, r1 = N - 1 - p;
    int len0 = N - 1 - r0;
    int s0 = (p & 15) * 255;              // offsets 0,255,...,3825

    const float* D0 = g_d2 + (size_t)r0 * N + (r0 + 1);
    const float* L0 = L    + (size_t)r0 * N + (r0 + 1);
    const float* D1 = g_d2 + (size_t)r1 * N + (r1 + 1);
    const float* L1 = L    + (size_t)r1 * N + (r1 + 1);

    if (tid < 256) {
        int e = s0 + tid;
        float d, l;
        if (e < len0) { d = D0[e]; l = L0[e]; }
        else          { d = D1[e - len0]; l = L1[e - len0]; }
        sDL[tid] = make_float2(-d, l);
    }
    __syncthreads();

    bool has5 = (w < 11);
    float c[5], a1[5], a2[5];
    #pragma unroll
    for (int j = 0; j < 4; j++) { c[j] = sc[w + 16 * j]; a1[j] = 0.0f; a2[j] = 0.0f; }
    c[4] = has5 ? sc[64 + w] : 0.0f;
    a1[4] = 0.0f; a2[4] = 0.0f;

    if (has5) {
        for (int e = lane; e < 256; e += 32) {
            float2 dl = sDL[e];
            #pragma unroll
            for (int j = 0; j < 5; j++) {
                float K;
                asm("ex2.approx.ftz.f32 %0, %1;" : "=f"(K) : "f"(dl.x * c[j]));
                a1[j] = fmaf(K, dl.y, a1[j]);
                a2[j] = fmaf(K, K,  a2[j]);
            }
        }
    } else {
        for (int e = lane; e < 256; e += 32) {
            float2 dl = sDL[e];
            #pragma unroll
            for (int j = 0; j < 4; j++) {
                float K;
                asm("ex2.approx.ftz.f32 %0, %1;" : "=f"(K) : "f"(dl.x * c[j]));
                a1[j] = fmaf(K, dl.y, a1[j]);
                a2[j] = fmaf(K, K,  a2[j]);
            }
        }
    }

    #pragma unroll
    for (int j = 0; j < 5; j++) {
        float v1 = a1[j], v2 = a2[j];
        #pragma unroll
        for (int o = 16; o; o >>= 1) {
            v1 += __shfl_xor_sync(0xffffffffu, v1, o);
            v2 += __shfl_xor_sync(0xffffffffu, v2, o);
        }
        if (lane == 0 && (j < 4 || has5)) {
            int idx = (j < 4) ? (w + 16 * j) : (64 + w);
            atomicAdd(&g_acc.S1[slot][idx], 2.0 * (double)v1);
            atomicAdd(&g_acc.S2[slot][idx], 2.0 * (double)v2);
        }
    }
}

// ---------------- fold slots + pick top-NC candidates ----------------------
__global__ void k_pick() {
    __shared__ double sL[NS];
    int j = threadIdx.x;
    if (j < NS) {
        double s1 = 0.0, s2 = 0.0;
        for (int s = 0; s < NSLOT; s++) { s1 += g_acc.S1[s][j]; s2 += g_acc.S2[s][j]; }
        sL[j] = s1 / sqrt(s2);
    }
    __syncthreads();
    if (j != 0) return;

    float mean = (float)(g_acc.sum_dist / (double)g_acc.nz);
    float lo = 0.1f * mean;
    float st = (10.0f * mean - lo) / (float)NS;

    bool used[NS];
    for (int i = 0; i < NS; i++) used[i] = false;
    int sel[NC];
    for (int r = 0; r < NC; r++) {
        double best = -1.0e300; int bi = 0;
        for (int i = 0; i < NS; i++)
            if (!used[i] && sL[i] > best) { best = sL[i]; bi = i; }
        used[bi] = true;
        sel[r] = bi;
    }
    for (int i = 1; i < NC; i++) {              // sort ascending (first-max semantics)
        int v = sel[i], k = i;
        while (k > 0 && sel[k - 1] > v) { sel[k] = sel[k - 1]; k--; }
        sel[k] = v;
    }
    for (int r = 0; r < NC; r++) {
        g_acc.cand[r] = sel[r];
        float s = lo + st * (float)sel[r];
        g_acc.candc[r] = LOG2E / (s * s);
    }
}

// ---------------- PASS 2: exact sums for NC=4 candidates -------------------
// 16 warps = 4 element-quarters x 4 candidates (k = w&3, quarter = w>>2).
// Each element: 4 exps + 4 LDS visits (half of the NC=8 scheme).
__global__ __launch_bounds__(512, 3) void k_sweep2(const float* __restrict__ L) {
    __shared__ float2 sDL[N];     // 4095 used
    __shared__ float scc[NC];

    int tid = threadIdx.x;
    int bid = blockIdx.x;

    if (tid < NC) scc[tid] = g_acc.candc[tid];

    int w = tid >> 5, lane = tid & 31;

    if (bid >= N / 2) {
        __syncthreads();
        int k = bid - N / 2;
        float c = scc[k];
        float s1 = 0.0f, s2 = 0.0f;
        for (int i = tid; i < N; i += 512) {
            float d = g_d2[(size_t)i * N + i];
            float l = L[(size_t)i * N + i];
            float K = exp2f(-d * c);
            s1 = fmaf(K, l, s1);
            s2 = fmaf(K, K, s2);
        }
        #pragma unroll
        for (int o = 16; o; o >>= 1) {
            s1 += __shfl_xor_sync(0xffffffffu, s1, o);
            s2 += __shfl_xor_sync(0xffffffffu, s2, o);
        }
        __shared__ float sh1[16], sh2[16];
        if (lane == 0) { sh1[w] = s1; sh2[w] = s2; }
        __syncthreads();
        if (tid == 0) {
            float a = 0.0f, bq = 0.0f;
            #pragma unroll
            for (int i = 0; i < 16; i++) { a += sh1[i]; bq += sh2[i]; }
            atomicAdd(&g_acc.T1[k & (NSLOT - 1)][k], (double)a);
            atomicAdd(&g_acc.T2[k & (NSLOT - 1)][k], (double)bq);
        }
        return;
    }

    int slot = bid & (NSLOT - 1);
    int p = bid;
    int r0 = p, r1 = N - 1 - p;
    int len0 = N - 1 - r0;

    const float* Dr0 = g_d2 + (size_t)r0 * N;
    const float* Lr0 = L    + (size_t)r0 * N;
    const float* Dr1 = g_d2 + (size_t)r1 * N;
    const float* Lr1 = L    + (size_t)r1 * N;

    int c00 = r0 + 1;
    for (int i4 = (c00 & ~3) + tid * 4; i4 < N; i4 += 512 * 4) {
        float4 d = *(const float4*)(Dr0 + i4);
        float4 l = *(const float4*)(Lr0 + i4);
        float dv[4] = {d.x, d.y, d.z, d.w};
        float lv[4] = {l.x, l.y, l.z, l.w};
        #pragma unroll
        for (int j = 0; j < 4; j++) {
            int col = i4 + j;
            if (col >= c00) sDL[col - c00] = make_float2(-dv[j], lv[j]);
        }
    }
    int c10 = r1 + 1;
    for (int i4 = (c10 & ~3) + tid * 4; i4 < N; i4 += 512 * 4) {
        float4 d = *(const float4*)(Dr1 + i4);
        float4 l = *(const float4*)(Lr1 + i4);
        float dv[4] = {d.x, d.y, d.z, d.w};
        float lv[4] = {l.x, l.y, l.z, l.w};
        #pragma unroll
        for (int j = 0; j < 4; j++) {
            int col = i4 + j;
            if (col >= c10) sDL[len0 + col - c10] = make_float2(-dv[j], lv[j]);
        }
    }
    __syncthreads();

    int k = w & 3;                 // candidate
    float c = scc[k];
    float a1 = 0.0f, a2 = 0.0f, b1 = 0.0f, b2 = 0.0f;
    int base = lane + 32 * (w >> 2);   // quarter origin
    for (int e = base; e < N - 1; e += 256) {
        float2 dl = sDL[e];
        float K;
        asm("ex2.approx.ftz.f32 %0, %1;" : "=f"(K) : "f"(dl.x * c));
        a1 = fmaf(K, dl.y, a1);
        a2 = fmaf(K, K, a2);
        int e2 = e + 128;
        if (e2 < N - 1) {
            float2 dl2 = sDL[e2];
            float K2;
            asm("ex2.approx.ftz.f32 %0, %1;" : "=f"(K2) : "f"(dl2.x * c));
            b1 = fmaf(K2, dl2.y, b1);
            b2 = fmaf(K2, K2, b2);
        }
    }
    a1 += b1; a2 += b2;
    #pragma unroll
    for (int o = 16; o; o >>= 1) {
        a1 += __shfl_xor_sync(0xffffffffu, a1, o);
        a2 += __shfl_xor_sync(0xffffffffu, a2, o);
    }
    if (lane == 0) {
        atomicAdd(&g_acc.T1[slot][k], 2.0 * (double)a1);
        atomicAdd(&g_acc.T2[slot][k], 2.0 * (double)a2);
    }
}

// ---------------- output: A = exp(-d2/sigma^2)/n, triangular + mirror ------
__global__ __launch_bounds__(256) void k_out(float* __restrict__ out) {
    __shared__ float s_cc;
    int tid = threadIdx.x;

    if (tid == 0) {
        float mean = (float)(g_acc.sum_dist / (double)g_acc.nz);
        float lo = 0.1f * mean;
        float st = (10.0f * mean - lo) / (float)NS;
        double best = -1.0e300;
        int bidx = 0;
        #pragma unroll 1
        for (int k = 0; k < NC; k++) {
            double t1 = 0.0, t2 = 0.0;
            for (int s = 0; s < NSLOT; s++) { t1 += g_acc.T1[s][k]; t2 += g_acc.T2[s][k]; }
            double l = t1 / sqrt(t2);
            if (l > best) { best = l; bidx = g_acc.cand[k]; }
        }
        float s = lo + st * (float)bidx;
        s_cc = -LOG2E / (s * s);
    }
    __syncthreads();
    float cc = s_cc;
    const float inv_n = 1.0f / (float)N;

    int b = blockIdx.x;
    float bf = (sqrtf(8.0f * (float)b + 1.0f) - 1.0f) * 0.5f;
    int bi = (int)bf;
    while ((bi + 1) * (bi + 2) / 2 <= b) bi++;
    while (bi * (bi + 1) / 2 > b) bi--;
    int bj = b - bi * (bi + 1) / 2;           // bi >= bj
    int tr = bj, tc = bi;

    if (tr == tc) {
        #pragma unroll
        for (int it = 0; it < 16; it++) {
            int e = (it * 256 + tid) * 4;
            int row = e >> 7;
            int col = e & 127;
            size_t g = (size_t)(tr * 128 + row) * N + tc * 128 + col;
            float4 d = *(const float4*)(g_d2 + g);
            float4 r;
            asm("ex2.approx.ftz.f32 %0, %1;" : "=f"(r.x) : "f"(d.x * cc));
            asm("ex2.approx.ftz.f32 %0, %1;" : "=f"(r.y) : "f"(d.y * cc));
            asm("ex2.approx.ftz.f32 %0, %1;" : "=f"(r.z) : "f"(d.z * cc));
            asm("ex2.approx.ftz.f32 %0, %1;" : "=f"(r.w) : "f"(d.w * cc));
            r.x *= inv_n; r.y *= inv_n; r.z *= inv_n; r.w *= inv_n;
            *(float4*)(out + g) = r;
        }
        return;
    }

    __shared__ float sT[64][65];
    #pragma unroll
    for (int q = 0; q < 4; q++) {
        int qr = q >> 1, qc = q & 1;
        int rbase = tr * 128 + qr * 64;
        int cbase = tc * 128 + qc * 64;
        #pragma unroll
        for (int it = 0; it < 4; it++) {
            int idx = it * 256 + tid;
            int row = idx >> 4;
            int col = (idx & 15) * 4;
            size_t g = (size_t)(rbase + row) * N + cbase + col;
            float4 d = *(const float4*)(g_d2 + g);
            float4 r;
            asm("ex2.approx.ftz.f32 %0, %1;" : "=f"(r.x) : "f"(d.x * cc));
            asm("ex2.approx.ftz.f32 %0, %1;" : "=f"(r.y) : "f"(d.y * cc));
            asm("ex2.approx.ftz.f32 %0, %1;" : "=f"(r.z) : "f"(d.z * cc));
            asm("ex2.approx.ftz.f32 %0, %1;" : "=f"(r.w) : "f"(d.w * cc));
            r.x *= inv_n; r.y *= inv_n; r.z *= inv_n; r.w *= inv_n;
            *(float4*)(out + g) = r;
            sT[row][col + 0] = r.x; sT[row][col + 1] = r.y;
            sT[row][col + 2] = r.z; sT[row][col + 3] = r.w;
        }
        __syncthreads();
        #pragma unroll
        for (int it = 0; it < 4; it++) {
            int idx = it * 256 + tid;
            int row = idx >> 4;
            int col = (idx & 15) * 4;
            size_t g = (size_t)(cbase + row) * N + rbase + col;
            float4 r = make_float4(sT[col + 0][row], sT[col + 1][row],
                                   sT[col + 2][row], sT[col + 3][row]);
            *(float4*)(out + g) = r;
        }
        __syncthreads();
    }
}

// ---------------- launch ----------------------------------------------------
extern "C" void kernel_launch(void* const* d_in, const int* in_sizes, int n_in,
                              void* d_out, int out_size) {
    (void)in_sizes; (void)n_in; (void)out_size;
    const float* x = (const float*)d_in[0];
    const float* L = (const float*)d_in[1];
    float* out = (float*)d_out;

    void* acc_ptr = nullptr;
    cudaGetSymbolAddress(&acc_ptr, g_acc);
    cudaMemsetAsync(acc_ptr, 0, sizeof(Accum));

    k_d2<<<(32 * 33) / 2, 256>>>(x);           // 528 tiles, scalar FFMA (proven)
    k_sweep1<<<N / 2 + NS, 512>>>(L);          // screening: 1/16 windows
    k_pick<<<1, 128>>>();                      // fold slots + top-4 candidates
    k_sweep2<<<N / 2 + NC, 512>>>(L);          // exact sums, 4 candidates
    k_out<<<(32 * 33) / 2, 256>>>(out);        // tiles + mirrors (+exact argmax)
}

// round 16
// speedup vs baseline: 1.1542x; 1.0144x over previous
#include <cuda_runtime.h>
#include <cstdint>
#include <math.h>

#define N 4096
#define D 128
#define NS 75
#define NC 4                     // candidate sigmas kept for exact pass
#define NSLOT 32                 // atomic accumulator slots
#define LOG2E 1.4426950408889634f

// ---------------- scratch (device globals; no runtime allocation) ----------
__device__ float g_d2[(size_t)N * N];      // upper-triangle tiles + diagonal tiles

struct Accum {
    double sum_dist;
    unsigned long long nz;
    double S1[NSLOT][NS], S2[NSLOT][NS];   // pass-1 sums, slot-spread
    double T1[NSLOT][NC], T2[NSLOT][NC];   // pass-2 exact sums, slot-spread
    int    cand[NC];
    float  candc[NC];
};
__device__ Accum g_acc;                    // zeroed via cudaMemsetAsync per launch

// bank-swizzle: row r (0..127) -> physical float index
__device__ __forceinline__ int swz(int r) {
    int q = r >> 2;
    return (((q ^ (q >> 3)) << 2) | (r & 3));
}
__device__ __forceinline__ int swzq(int q) {
    return (q ^ (q >> 3)) << 2;
}

// ---------------- d2 GEMM (scalar FFMA, proven 76us; R10 form) -------------
__global__ __launch_bounds__(256) void k_d2(const float* __restrict__ x) {
    int b = blockIdx.x;
    float bf = (sqrtf(8.0f * (float)b + 1.0f) - 1.0f) * 0.5f;
    int bi = (int)bf;
    while ((bi + 1) * (bi + 2) / 2 <= b) bi++;
    while (bi * (bi + 1) / 2 > b) bi--;
    int bj = b - bi * (bi + 1) / 2;           // bi >= bj

    __shared__ __align__(16) float As[8][128];
    __shared__ __align__(16) float Bs[8][128];

    int tid = threadIdx.x;
    int tx = tid & 15;
    int ty = tid >> 4;
    int lr = tid >> 1;
    int lc = (tid & 1) * 4;

    const float* Ab = x + (size_t)bi * 128 * D;
    const float* Bb = x + (size_t)bj * 128 * D;

    float acc[8][8];
    #pragma unroll
    for (int m = 0; m < 8; m++)
        #pragma unroll
        for (int n = 0; n < 8; n++) acc[m][n] = 0.0f;

    float sa = 0.0f, sb = 0.0f;
    int plr = swz(lr);

    const int pqa0 = swzq(ty * 2), pqa1 = swzq(ty * 2 + 1);
    const int pqb0 = swzq(tx * 2), pqb1 = swzq(tx * 2 + 1);

    for (int k0 = 0; k0 < D; k0 += 8) {
        float4 av = *(const float4*)(Ab + (size_t)lr * D + k0 + lc);
        float4 bv = *(const float4*)(Bb + (size_t)lr * D + k0 + lc);
        sa = fmaf(av.x, av.x, fmaf(av.y, av.y, fmaf(av.z, av.z, fmaf(av.w, av.w, sa))));
        sb = fmaf(bv.x, bv.x, fmaf(bv.y, bv.y, fmaf(bv.z, bv.z, fmaf(bv.w, bv.w, sb))));
        As[lc + 0][plr] = av.x; As[lc + 1][plr] = av.y;
        As[lc + 2][plr] = av.z; As[lc + 3][plr] = av.w;
        Bs[lc + 0][plr] = bv.x; Bs[lc + 1][plr] = bv.y;
        Bs[lc + 2][plr] = bv.z; Bs[lc + 3][plr] = bv.w;
        __syncthreads();
        #pragma unroll
        for (int k = 0; k < 8; k++) {
            float4 a0 = *(const float4*)&As[k][pqa0];
            float4 a1 = *(const float4*)&As[k][pqa1];
            float4 b0 = *(const float4*)&Bs[k][pqb0];
            float4 b1 = *(const float4*)&Bs[k][pqb1];
            float a[8] = {a0.x, a0.y, a0.z, a0.w, a1.x, a1.y, a1.z, a1.w};
            float bb[8] = {b0.x, b0.y, b0.z, b0.w, b1.x, b1.y, b1.z, b1.w};
            #pragma unroll
            for (int m = 0; m < 8; m++)
                #pragma unroll
                for (int n = 0; n < 8; n++)
                    acc[m][n] = fmaf(a[m], bb[n], acc[m][n]);
        }
        __syncthreads();
    }

    sa += __shfl_xor_sync(0xffffffffu, sa, 1);
    sb += __shfl_xor_sync(0xffffffffu, sb, 1);
    float* sqA = &As[0][0];
    float* sqB = &Bs[0][0];
    if ((tid & 1) == 0) { sqA[lr] = sa; sqB[lr] = sb; }
    __syncthreads();

    int row0 = bi * 128 + ty * 8;
    int col0 = bj * 128 + tx * 8;
    float sqi[8], sqj[8];
    #pragma unroll
    for (int m = 0; m < 8; m++) sqi[m] = sqA[ty * 8 + m];
    #pragma unroll
    for (int n = 0; n < 8; n++) sqj[n] = sqB[tx * 8 + n];

    float sd = 0.0f;
    int cnt = 0;

    if (bi == bj) {
        #pragma unroll
        for (int m = 0; m < 8; m++) {
            float v[8];
            #pragma unroll
            for (int n = 0; n < 8; n++) {
                float dd = fmaxf(sqi[m] + sqj[n] - 2.0f * acc[m][n], 0.0f);
                v[n] = dd;
                if (dd > 0.0f) { sd += sqrtf(dd); cnt++; }
            }
            float4* p = (float4*)&g_d2[(size_t)(row0 + m) * N + col0];
            p[0] = make_float4(v[0], v[1], v[2], v[3]);
            p[1] = make_float4(v[4], v[5], v[6], v[7]);
        }
    } else {
        #pragma unroll
        for (int n = 0; n < 8; n++) {
            float t[8];
            #pragma unroll
            for (int m = 0; m < 8; m++) {
                float dd = fmaxf(sqi[m] + sqj[n] - 2.0f * acc[m][n], 0.0f);
                t[m] = dd;
                if (dd > 0.0f) { sd += sqrtf(dd); cnt++; }
            }
            float4* p = (float4*)&g_d2[(size_t)(col0 + n) * N + row0];
            p[0] = make_float4(t[0], t[1], t[2], t[3]);
            p[1] = make_float4(t[4], t[5], t[6], t[7]);
        }
    }

    #pragma unroll
    for (int o = 16; o; o >>= 1) {
        sd  += __shfl_xor_sync(0xffffffffu, sd, o);
        cnt += __shfl_xor_sync(0xffffffffu, cnt, o);
    }
    __shared__ float ssd[8];
    __shared__ int   scn[8];
    int wid = tid >> 5;
    if ((tid & 31) == 0) { ssd[wid] = sd; scn[wid] = cnt; }
    __syncthreads();
    if (tid == 0) {
        float S = 0.0f; long long C = 0;
        #pragma unroll
        for (int i = 0; i < 8; i++) { S += ssd[i]; C += scn[i]; }
        double w = (bi == bj) ? 1.0 : 2.0;
        atomicAdd(&g_acc.sum_dist, w * (double)S);
        atomicAdd(&g_acc.nz, (unsigned long long)((bi == bj ? 1 : 2) * C));
    }
}

// ---------------- PASS 1: screening sweep on contiguous 128-elem windows ---
// 1/32 deterministic subsample; window offset (p&31)*127 spans the pair.
// Diagonal scaled 1/32 to stay proportional to true 2U + Dg.
__global__ __launch_bounds__(512, 3) void k_sweep1(const float* __restrict__ L) {
    __shared__ float2 sDL[128];
    __shared__ float sc[80];

    int tid = threadIdx.x;
    int bid = blockIdx.x;

    if (tid < 80) {
        float mean = (float)(g_acc.sum_dist / (double)g_acc.nz);
        float lo = 0.1f * mean;
        float st = (10.0f * mean - lo) / (float)NS;
        float s = lo + st * (float)tid;
        sc[tid] = (tid < NS) ? LOG2E / (s * s) : 0.0f;
    }

    int w = tid >> 5, lane = tid & 31;

    if (bid >= N / 2) {
        // ---- diagonal block for sigma j (scaled 1/32) ----
        __syncthreads();
        int j = bid - N / 2;
        float c = sc[j];
        float s1 = 0.0f, s2 = 0.0f;
        for (int i = tid; i < N; i += 512) {
            float d = g_d2[(size_t)i * N + i];
            float l = L[(size_t)i * N + i];
            float K = exp2f(-d * c);
            s1 = fmaf(K, l, s1);
            s2 = fmaf(K, K, s2);
        }
        #pragma unroll
        for (int o = 16; o; o >>= 1) {
            s1 += __shfl_xor_sync(0xffffffffu, s1, o);
            s2 += __shfl_xor_sync(0xffffffffu, s2, o);
        }
        __shared__ float sh1[16], sh2[16];
        if (lane == 0) { sh1[w] = s1; sh2[w] = s2; }
        __syncthreads();
        if (tid == 0) {
            float a = 0.0f, bq = 0.0f;
            #pragma unroll
            for (int i = 0; i < 16; i++) { a += sh1[i]; bq += sh2[i]; }
            atomicAdd(&g_acc.S1[j & (NSLOT - 1)][j], 0.03125 * (double)a);
            atomicAdd(&g_acc.S2[j & (NSLOT - 1)][j], 0.03125 * (double)bq);
        }
        return;
    }

    int slot = bid & (NSLOT - 1);
    int p = bid;
    int r0 = p, r1 = N - 1 - p;
    int len0 = N - 1 - r0;
    int s0 = (p & 31) * 127;              // offsets 0,127,...,3937 (max e 4064)

    const float* D0 = g_d2 + (size_t)r0 * N + (r0 + 1);
    const float* L0 = L    + (size_t)r0 * N + (r0 + 1);
    const float* D1 = g_d2 + (size_t)r1 * N + (r1 + 1);
    const float* L1 = L    + (size_t)r1 * N + (r1 + 1);

    if (tid < 128) {
        int e = s0 + tid;
        float d, l;
        if (e < len0) { d = D0[e]; l = L0[e]; }
        else          { d = D1[e - len0]; l = L1[e - len0]; }
        sDL[tid] = make_float2(-d, l);
    }
    __syncthreads();

    bool has5 = (w < 11);
    float c[5], a1[5], a2[5];
    #pragma unroll
    for (int j = 0; j < 4; j++) { c[j] = sc[w + 16 * j]; a1[j] = 0.0f; a2[j] = 0.0f; }
    c[4] = has5 ? sc[64 + w] : 0.0f;
    a1[4] = 0.0f; a2[4] = 0.0f;

    if (has5) {
        for (int e = lane; e < 128; e += 32) {
            float2 dl = sDL[e];
            #pragma unroll
            for (int j = 0; j < 5; j++) {
                float K;
                asm("ex2.approx.ftz.f32 %0, %1;" : "=f"(K) : "f"(dl.x * c[j]));
                a1[j] = fmaf(K, dl.y, a1[j]);
                a2[j] = fmaf(K, K,  a2[j]);
            }
        }
    } else {
        for (int e = lane; e < 128; e += 32) {
            float2 dl = sDL[e];
            #pragma unroll
            for (int j = 0; j < 4; j++) {
                float K;
                asm("ex2.approx.ftz.f32 %0, %1;" : "=f"(K) : "f"(dl.x * c[j]));
                a1[j] = fmaf(K, dl.y, a1[j]);
                a2[j] = fmaf(K, K,  a2[j]);
            }
        }
    }

    #pragma unroll
    for (int j = 0; j < 5; j++) {
        float v1 = a1[j], v2 = a2[j];
        #pragma unroll
        for (int o = 16; o; o >>= 1) {
            v1 += __shfl_xor_sync(0xffffffffu, v1, o);
            v2 += __shfl_xor_sync(0xffffffffu, v2, o);
        }
        if (lane == 0 && (j < 4 || has5)) {
            int idx = (j < 4) ? (w + 16 * j) : (64 + w);
            atomicAdd(&g_acc.S1[slot][idx], 2.0 * (double)v1);
            atomicAdd(&g_acc.S2[slot][idx], 2.0 * (double)v2);
        }
    }
}

// ---------------- fold slots + pick top-NC candidates ----------------------
__global__ void k_pick() {
    __shared__ double sL[NS];
    int j = threadIdx.x;
    if (j < NS) {
        double s1 = 0.0, s2 = 0.0;
        for (int s = 0; s < NSLOT; s++) { s1 += g_acc.S1[s][j]; s2 += g_acc.S2[s][j]; }
        sL[j] = s1 / sqrt(s2);
    }
    __syncthreads();
    if (j != 0) return;

    float mean = (float)(g_acc.sum_dist / (double)g_acc.nz);
    float lo = 0.1f * mean;
    float st = (10.0f * mean - lo) / (float)NS;

    bool used[NS];
    for (int i = 0; i < NS; i++) used[i] = false;
    int sel[NC];
    for (int r = 0; r < NC; r++) {
        double best = -1.0e300; int bi = 0;
        for (int i = 0; i < NS; i++)
            if (!used[i] && sL[i] > best) { best = sL[i]; bi = i; }
        used[bi] = true;
        sel[r] = bi;
    }
    for (int i = 1; i < NC; i++) {              // sort ascending (first-max semantics)
        int v = sel[i], k = i;
        while (k > 0 && sel[k - 1] > v) { sel[k] = sel[k - 1]; k--; }
        sel[k] = v;
    }
    for (int r = 0; r < NC; r++) {
        g_acc.cand[r] = sel[r];
        float s = lo + st * (float)sel[r];
        g_acc.candc[r] = LOG2E / (s * s);
    }
}

// ---------------- PASS 2: exact sums for NC=4 candidates -------------------
// 16 warps = 4 element-quarters x 4 candidates (k = w&3, quarter = w>>2).
__global__ __launch_bounds__(512, 3) void k_sweep2(const float* __restrict__ L) {
    __shared__ float2 sDL[N];     // 4095 used
    __shared__ float scc[NC];

    int tid = threadIdx.x;
    int bid = blockIdx.x;

    if (tid < NC) scc[tid] = g_acc.candc[tid];

    int w = tid >> 5, lane = tid & 31;

    if (bid >= N / 2) {
        __syncthreads();
        int k = bid - N / 2;
        float c = scc[k];
        float s1 = 0.0f, s2 = 0.0f;
        for (int i = tid; i < N; i += 512) {
            float d = g_d2[(size_t)i * N + i];
            float l = L[(size_t)i * N + i];
            float K = exp2f(-d * c);
            s1 = fmaf(K, l, s1);
            s2 = fmaf(K, K, s2);
        }
        #pragma unroll
        for (int o = 16; o; o >>= 1) {
            s1 += __shfl_xor_sync(0xffffffffu, s1, o);
            s2 += __shfl_xor_sync(0xffffffffu, s2, o);
        }
        __shared__ float sh1[16], sh2[16];
        if (lane == 0) { sh1[w] = s1; sh2[w] = s2; }
        __syncthreads();
        if (tid == 0) {
            float a = 0.0f, bq = 0.0f;
            #pragma unroll
            for (int i = 0; i < 16; i++) { a += sh1[i]; bq += sh2[i]; }
            atomicAdd(&g_acc.T1[k & (NSLOT - 1)][k], (double)a);
            atomicAdd(&g_acc.T2[k & (NSLOT - 1)][k], (double)bq);
        }
        return;
    }

    int slot = bid & (NSLOT - 1);
    int p = bid;
    int r0 = p, r1 = N - 1 - p;
    int len0 = N - 1 - r0;

    const float* Dr0 = g_d2 + (size_t)r0 * N;
    const float* Lr0 = L    + (size_t)r0 * N;
    const float* Dr1 = g_d2 + (size_t)r1 * N;
    const float* Lr1 = L    + (size_t)r1 * N;

    int c00 = r0 + 1;
    for (int i4 = (c00 & ~3) + tid * 4; i4 < N; i4 += 512 * 4) {
        float4 d = *(const float4*)(Dr0 + i4);
        float4 l = *(const float4*)(Lr0 + i4);
        float dv[4] = {d.x, d.y, d.z, d.w};
        float lv[4] = {l.x, l.y, l.z, l.w};
        #pragma unroll
        for (int j = 0; j < 4; j++) {
            int col = i4 + j;
            if (col >= c00) sDL[col - c00] = make_float2(-dv[j], lv[j]);
        }
    }
    int c10 = r1 + 1;
    for (int i4 = (c10 & ~3) + tid * 4; i4 < N; i4 += 512 * 4) {
        float4 d = *(const float4*)(Dr1 + i4);
        float4 l = *(const float4*)(Lr1 + i4);
        float dv[4] = {d.x, d.y, d.z, d.w};
        float lv[4] = {l.x, l.y, l.z, l.w};
        #pragma unroll
        for (int j = 0; j < 4; j++) {
            int col = i4 + j;
            if (col >= c10) sDL[len0 + col - c10] = make_float2(-dv[j], lv[j]);
        }
    }
    __syncthreads();

    int k = w & 3;                 // candidate
    float c = scc[k];
    float a1 = 0.0f, a2 = 0.0f, b1 = 0.0f, b2 = 0.0f;
    int base = lane + 32 * (w >> 2);   // quarter origin
    for (int e = base; e < N - 1; e += 256) {
        float2 dl = sDL[e];
        float K;
        asm("ex2.approx.ftz.f32 %0, %1;" : "=f"(K) : "f"(dl.x * c));
        a1 = fmaf(K, dl.y, a1);
        a2 = fmaf(K, K, a2);
        int e2 = e + 128;
        if (e2 < N - 1) {
            float2 dl2 = sDL[e2];
            float K2;
            asm("ex2.approx.ftz.f32 %0, %1;" : "=f"(K2) : "f"(dl2.x * c));
            b1 = fmaf(K2, dl2.y, b1);
            b2 = fmaf(K2, K2, b2);
        }
    }
    a1 += b1; a2 += b2;
    #pragma unroll
    for (int o = 16; o; o >>= 1) {
        a1 += __shfl_xor_sync(0xffffffffu, a1, o);
        a2 += __shfl_xor_sync(0xffffffffu, a2, o);
    }
    if (lane == 0) {
        atomicAdd(&g_acc.T1[slot][k], 2.0 * (double)a1);
        atomicAdd(&g_acc.T2[slot][k], 2.0 * (double)a2);
    }
}

// ---------------- output: one 64x64 quadrant per block ---------------------
// grid = 528*4: block = (128-tile pair) * quadrant. Diagonal 128-blocks are
// stored full -> all quadrants write direct. Off-diag quadrants: direct +
// transposed mirror through one 64x65 smem stage (single sync per block).
__global__ __launch_bounds__(256) void k_out(float* __restrict__ out) {
    __shared__ float s_cc;
    int tid = threadIdx.x;

    if (tid == 0) {
        float mean = (float)(g_acc.sum_dist / (double)g_acc.nz);
        float lo = 0.1f * mean;
        float st = (10.0f * mean - lo) / (float)NS;
        double best = -1.0e300;
        int bidx = 0;
        #pragma unroll 1
        for (int k = 0; k < NC; k++) {
            double t1 = 0.0, t2 = 0.0;
            for (int s = 0; s < NSLOT; s++) { t1 += g_acc.T1[s][k]; t2 += g_acc.T2[s][k]; }
            double l = t1 / sqrt(t2);
            if (l > best) { best = l; bidx = g_acc.cand[k]; }
        }
        float s = lo + st * (float)bidx;
        s_cc = -LOG2E / (s * s);
    }
    __syncthreads();
    float cc = s_cc;
    const float inv_n = 1.0f / (float)N;

    int b = blockIdx.x >> 2;
    int q = blockIdx.x & 3;
    float bf = (sqrtf(8.0f * (float)b + 1.0f) - 1.0f) * 0.5f;
    int bi = (int)bf;
    while ((bi + 1) * (bi + 2) / 2 <= b) bi++;
    while (bi * (bi + 1) / 2 > b) bi--;
    int bj = b - bi * (bi + 1) / 2;           // bi >= bj
    int qr = q >> 1, qc = q & 1;

    if (bi == bj) {
        // diagonal 128-block: fully stored; direct exp for this quadrant
        int rbase = bi * 128 + qr * 64;
        int cbase = bi * 128 + qc * 64;
        #pragma unroll
        for (int it = 0; it < 4; it++) {
            int idx = it * 256 + tid;
            int row = idx >> 4;
            int col = (idx & 15) * 4;
            size_t g = (size_t)(rbase + row) * N + cbase + col;
            float4 d = *(const float4*)(g_d2 + g);
            float4 r;
            asm("ex2.approx.ftz.f32 %0, %1;" : "=f"(r.x) : "f"(d.x * cc));
            asm("ex2.approx.ftz.f32 %0, %1;" : "=f"(r.y) : "f"(d.y * cc));
            asm("ex2.approx.ftz.f32 %0, %1;" : "=f"(r.z) : "f"(d.z * cc));
            asm("ex2.approx.ftz.f32 %0, %1;" : "=f"(r.w) : "f"(d.w * cc));
            r.x *= inv_n; r.y *= inv_n; r.z *= inv_n; r.w *= inv_n;
            *(float4*)(out + g) = r;
        }
        return;
    }

    // off-diag: stored quadrant at rows bj*128+qr*64, cols bi*128+qc*64
    __shared__ float sT[64][65];
    int rbase = bj * 128 + qr * 64;
    int cbase = bi * 128 + qc * 64;
    #pragma unroll
    for (int it = 0; it < 4; it++) {
        int idx = it * 256 + tid;
        int row = idx >> 4;
        int col = (idx & 15) * 4;
        size_t g = (size_t)(rbase + row) * N + cbase + col;
        float4 d = *(const float4*)(g_d2 + g);
        float4 r;
        asm("ex2.approx.ftz.f32 %0, %1;" : "=f"(r.x) : "f"(d.x * cc));
        asm("ex2.approx.ftz.f32 %0, %1;" : "=f"(r.y) : "f"(d.y * cc));
        asm("ex2.approx.ftz.f32 %0, %1;" : "=f"(r.z) : "f"(d.z * cc));
        asm("ex2.approx.ftz.f32 %0, %1;" : "=f"(r.w) : "f"(d.w * cc));
        r.x *= inv_n; r.y *= inv_n; r.z *= inv_n; r.w *= inv_n;
        *(float4*)(out + g) = r;
        sT[row][col + 0] = r.x; sT[row][col + 1] = r.y;
        sT[row][col + 2] = r.z; sT[row][col + 3] = r.w;
    }
    __syncthreads();
    // mirror: rows bi*128+qc*64, cols bj*128+qr*64 (transposed quadrant)
    #pragma unroll
    for (int it = 0; it < 4; it++) {
        int idx = it * 256 + tid;
        int row = idx >> 4;
        int col = (idx & 15) * 4;
        size_t g = (size_t)(cbase + row) * N + rbase + col;
        float4 r = make_float4(sT[col + 0][row], sT[col + 1][row],
                               sT[col + 2][row], sT[col + 3][row]);
        *(float4*)(out + g) = r;
    }
}

// ---------------- launch ----------------------------------------------------
extern "C" void kernel_launch(void* const* d_in, const int* in_sizes, int n_in,
                              void* d_out, int out_size) {
    (void)in_sizes; (void)n_in; (void)out_size;
    const float* x = (const float*)d_in[0];
    const float* L = (const float*)d_in[1];
    float* out = (float*)d_out;

    void* acc_ptr = nullptr;
    cudaGetSymbolAddress(&acc_ptr, g_acc);
    cudaMemsetAsync(acc_ptr, 0, sizeof(Accum));

    k_d2<<<(32 * 33) / 2, 256>>>(x);           // 528 tiles, scalar FFMA (proven)
    k_sweep1<<<N / 2 + NS, 512>>>(L);          // screening: 1/32 windows
    k_pick<<<1, 128>>>();                      // fold slots + top-4 candidates
    k_sweep2<<<N / 2 + NC, 512>>>(L);          // exact sums, 4 candidates
    k_out<<<(32 * 33) / 2 * 4, 256>>>(out);    // 64x64 quadrants + mirrors
}